// round 16
// baseline (speedup 1.0000x reference)
#include <cuda_runtime.h>
#include <cuda_fp16.h>
#include <cstdint>
#include <math.h>

// Problem shape (fixed)
#define NB   4
#define SEQ  2048
#define DIN  1024
#define DH   1024

// ---------------------------------------------------------------------------
// Scratch (__device__ globals; no allocs allowed)
// ---------------------------------------------------------------------------
__device__ __half g_xh [(size_t)NB * SEQ * DIN];      // fp16 x            (16 MB)
__device__ __half g_Wqk[(size_t)2 * DH * DIN];        // [Wq; Wk] fp16     (4 MB)
__device__ __half g_Wv [(size_t)DH * DIN];            // fp16              (2 MB)
__device__ __half g_QK [(size_t)NB * SEQ * 2 * DH];   // [Q | K] fp16      (32 MB)
__device__ __half g_Vt [(size_t)NB * DH * SEQ];       // V^T fp16          (16 MB)
__device__ __half g_At [(size_t)NB * SEQ * SEQ];      // exp-scores fp16   (32 MB)
__device__ float  g_Part[(size_t)16 * NB * SEQ];      // row partials      (512 KB)

// Work-queue + dependency counters
__device__ int g_qhead;
__device__ int g_cntQK[64];     // QK row-blocks (z*16+by), target 16
__device__ int g_cntVt[32];     // Vt row-blocks (z*8+y),  target 16
__device__ int g_cntSc[64];     // At row-blocks (z*16+by), target 16

constexpr int N_PROJ_QK = 1024;                 // idx [0, 1024)
constexpr int N_VT      = 512;                  // idx [1024, 1536)
constexpr int N_SCORES  = 1024;                 // idx [1536, 2560)
constexpr int N_PV      = 512;                  // idx [2560, 3072)
constexpr int N_TILES   = N_PROJ_QK + N_VT + N_SCORES + N_PV;

// ---------------------------------------------------------------------------
__device__ __forceinline__ uint32_t smem_u32(const void* p) {
    uint32_t a;
    asm("{ .reg .u64 t; cvta.to.shared.u64 t, %1; cvt.u32.u64 %0, t; }"
        : "=r"(a) : "l"(p));
    return a;
}

#define LDMATRIX_X4(r0, r1, r2, r3, addr)                                      \
    asm volatile("ldmatrix.sync.aligned.m8n8.x4.shared.b16 {%0,%1,%2,%3}, [%4];" \
                 : "=r"(r0), "=r"(r1), "=r"(r2), "=r"(r3) : "r"(addr))

// ---------------------------------------------------------------------------
// fp16 m16n8k16 NT GEMM body (unchanged from R15).
// ---------------------------------------------------------------------------
constexpr int BM = 128, BN = 128, BK = 64, NST = 3;
constexpr int TILE_H  = BM * BK;
constexpr int STAGE_H = 2 * TILE_H;
constexpr int SMEM_BYTES = NST * STAGE_H * 2;    // 98304 B

template <bool OUT_HALF>
__device__ __forceinline__
void gemm_body(const __half* __restrict__ Ab, const __half* __restrict__ Bb,
               void* __restrict__ Cb, int K,
               int ldA, int ldB, int ldC, float alpha,
               int bm, int bn, int doExp,
               const float* __restrict__ partIn,
               float* __restrict__ partOut)
{
    extern __shared__ __align__(16) __half sm[];

    const int tid  = threadIdx.x;
    const int wid  = tid >> 5;
    const int lane = tid & 31;
    const int g    = lane >> 2;
    const int tig  = lane & 3;

    const int wm = wid >> 2;
    const int wn = wid & 3;
    const int KT = K / BK;

    const uint32_t smem_base = smem_u32(sm);

    const int xorv = lane & 7;
    const int rowA = wm * 64 + (lane & 7) + ((lane >> 3) & 1) * 8;
    const int selA = lane >> 4;
    const int rowB = wn * 32 + (lane & 7) + ((lane >> 4) & 1) * 8;
    const int selB = (lane >> 3) & 1;

#define LOAD_CHUNK(s, i) do {                                                  \
        const uint32_t _base = smem_base + (uint32_t)(((s) % NST) * STAGE_H * 2); \
        const uint32_t _bB   = _base + (uint32_t)(TILE_H * 2);                 \
        const int _idx = (i) * 256 + tid;                                      \
        const int _row = _idx >> 3;                                            \
        const int _seg = _idx & 7;                                             \
        const uint32_t _soff = (uint32_t)(_row * 128 +                         \
                               ((_seg ^ (_row & 7)) << 4));                    \
        const __half* _ga = Ab + (uint32_t)(bm + _row) * (uint32_t)ldA         \
                               + (uint32_t)((s) * BK + _seg * 8);              \
        const __half* _gb = Bb + (uint32_t)(bn + _row) * (uint32_t)ldB         \
                               + (uint32_t)((s) * BK + _seg * 8);              \
        asm volatile("cp.async.cg.shared.global [%0], [%1], 16;"               \
                     :: "r"(_base + _soff), "l"(_ga));                         \
        asm volatile("cp.async.cg.shared.global [%0], [%1], 16;"               \
                     :: "r"(_bB + _soff), "l"(_gb));                           \
    } while (0)

#define LOAD_STAGE(s) do {                                                     \
        LOAD_CHUNK(s, 0); LOAD_CHUNK(s, 1); LOAD_CHUNK(s, 2); LOAD_CHUNK(s, 3);\
        asm volatile("cp.async.commit_group;" ::: "memory");                   \
    } while (0)

    float acc[4][4][4];
    #pragma unroll
    for (int i = 0; i < 4; i++)
        #pragma unroll
        for (int j = 0; j < 4; j++)
            #pragma unroll
            for (int r = 0; r < 4; r++) acc[i][j][r] = 0.0f;

    LOAD_STAGE(0);
    LOAD_STAGE(1);

    for (int k0 = 0; k0 < KT; k0++) {
        if (k0 + 1 < KT) asm volatile("cp.async.wait_group 1;" ::: "memory");
        else             asm volatile("cp.async.wait_group 0;" ::: "memory");
        __syncthreads();

        const bool doLoad = (k0 + 2 < KT);
        const uint32_t stA = smem_base + (uint32_t)((k0 % NST) * STAGE_H * 2);
        const uint32_t stB = stA + (uint32_t)(TILE_H * 2);
        const uint32_t aRowAddr = stA + (uint32_t)(rowA * 128);
        const uint32_t bRowAddr = stB + (uint32_t)(rowB * 128);

        #pragma unroll
        for (int ks = 0; ks < BK / 16; ks++) {
            if (doLoad) {
                LOAD_CHUNK(k0 + 2, ks);
                if (ks == 3)
                    asm volatile("cp.async.commit_group;" ::: "memory");
            }

            const uint32_t offA = (uint32_t)(((2 * ks + selA) ^ xorv) << 4);
            const uint32_t offB = (uint32_t)(((2 * ks + selB) ^ xorv) << 4);
            uint32_t a[4][4], b[4][2];
            #pragma unroll
            for (int p = 0; p < 2; p++)
                LDMATRIX_X4(b[2 * p][0], b[2 * p][1], b[2 * p + 1][0], b[2 * p + 1][1],
                            bRowAddr + (uint32_t)(p * 16 * 128) + offB);
            #pragma unroll
            for (int mf = 0; mf < 4; mf++)
                LDMATRIX_X4(a[mf][0], a[mf][1], a[mf][2], a[mf][3],
                            aRowAddr + (uint32_t)(mf * 16 * 128) + offA);
            #pragma unroll
            for (int mf = 0; mf < 4; mf++)
                #pragma unroll
                for (int nf = 0; nf < 4; nf++)
                    asm volatile(
                        "mma.sync.aligned.m16n8k16.row.col.f32.f16.f16.f32 "
                        "{%0,%1,%2,%3}, {%4,%5,%6,%7}, {%8,%9}, {%0,%1,%2,%3};"
                        : "+f"(acc[mf][nf][0]), "+f"(acc[mf][nf][1]),
                          "+f"(acc[mf][nf][2]), "+f"(acc[mf][nf][3])
                        : "r"(a[mf][0]), "r"(a[mf][1]), "r"(a[mf][2]), "r"(a[mf][3]),
                          "r"(b[nf][0]), "r"(b[nf][1]));
        }
    }
#undef LOAD_STAGE
#undef LOAD_CHUNK

    // Deferred-normalization reciprocal table (fp32-out path only)
    float* sinv = reinterpret_cast<float*>(sm);
    if (!OUT_HALF && partIn) {
        __syncthreads();
        if (tid < 128) {
            float s = 0.0f;
            #pragma unroll
            for (int t = 0; t < 16; t++)
                s += partIn[t * (NB * SEQ) + tid];
            sinv[tid] = 1.0f / s;
        }
        __syncthreads();
    }

    const uint32_t mBase = (uint32_t)(bm + wm * 64 + g);
    const uint32_t nBase = (uint32_t)(bn + wn * 32 + 2 * tig);
    float psum[4][2];
    #pragma unroll
    for (int mf = 0; mf < 4; mf++) { psum[mf][0] = 0.0f; psum[mf][1] = 0.0f; }

    #pragma unroll
    for (int mf = 0; mf < 4; mf++) {
        float ri0 = 1.0f, ri1 = 1.0f;
        if (!OUT_HALF && partIn) {
            ri0 = sinv[wm * 64 + mf * 16 + g];
            ri1 = sinv[wm * 64 + mf * 16 + g + 8];
        }
        #pragma unroll
        for (int nf = 0; nf < 4; nf++) {
            float v0 = acc[mf][nf][0] * alpha, v1 = acc[mf][nf][1] * alpha;
            float v2 = acc[mf][nf][2] * alpha, v3 = acc[mf][nf][3] * alpha;
            if (doExp) {
                v0 = __expf(v0); v1 = __expf(v1);
                v2 = __expf(v2); v3 = __expf(v3);
                psum[mf][0] += v0 + v1;
                psum[mf][1] += v2 + v3;
            }
            const uint32_t r0 = (mBase + mf * 16) * (uint32_t)ldC + nBase + nf * 8;
            const uint32_t r1 = r0 + 8 * (uint32_t)ldC;
            if (OUT_HALF) {
                __half* Ch = (__half*)Cb;
                *reinterpret_cast<__half2*>(&Ch[r0]) =
                    __float22half2_rn(make_float2(v0, v1));
                *reinterpret_cast<__half2*>(&Ch[r1]) =
                    __float22half2_rn(make_float2(v2, v3));
            } else {
                float* Cf = (float*)Cb;
                *reinterpret_cast<float2*>(&Cf[r0]) = make_float2(v0 * ri0, v1 * ri0);
                *reinterpret_cast<float2*>(&Cf[r1]) = make_float2(v2 * ri1, v3 * ri1);
            }
        }
    }

    if (doExp && partOut) {
        #pragma unroll
        for (int mf = 0; mf < 4; mf++) {
            #pragma unroll
            for (int h = 0; h < 2; h++) {
                psum[mf][h] += __shfl_xor_sync(0xFFFFFFFFu, psum[mf][h], 1);
                psum[mf][h] += __shfl_xor_sync(0xFFFFFFFFu, psum[mf][h], 2);
            }
        }
        __syncthreads();
        float* sp = reinterpret_cast<float*>(sm);
        if (tig == 0) {
            #pragma unroll
            for (int mf = 0; mf < 4; mf++) {
                sp[(wm * 64 + mf * 16 + g)     * 4 + wn] = psum[mf][0];
                sp[(wm * 64 + mf * 16 + g + 8) * 4 + wn] = psum[mf][1];
            }
        }
        __syncthreads();
        if (tid < 128) {
            const float* r = sp + tid * 4;
            partOut[tid] = (r[0] + r[1]) + (r[2] + r[3]);
        }
    }
}

// ---------------------------------------------------------------------------
// Persistent work-queue kernel: all four GEMM phases, fine-grained deps.
// Queue order: proj-QK [0,1024) -> Vt [1024,1536) -> scores [1536,2560)
//              -> PV [2560,3072).  Consumers spin on row-block counters.
// ---------------------------------------------------------------------------
__global__ __launch_bounds__(256, 2)
void attn_queue(const __half* __restrict__ xh, const __half* __restrict__ wqk,
                const __half* __restrict__ wv,
                __half* __restrict__ QK, __half* __restrict__ Vt,
                __half* __restrict__ At,
                float* __restrict__ part, float* __restrict__ out, float scale)
{
    __shared__ int s_idx;
    const int tid = threadIdx.x;

    for (;;) {
        if (tid == 0) s_idx = atomicAdd(&g_qhead, 1);
        __syncthreads();
        const int idx = s_idx;
        if (idx >= N_TILES) return;

        if (idx < N_PROJ_QK + N_VT + N_SCORES) {
            // ----- fp16-out phases: proj-QK / Vt / exp-scores -----
            const __half *A, *B;
            __half* C;
            int K, ldA, ldB, ldC, bm, bn, doExp;
            float alpha;
            float* pOut;
            int* cnt;

            if (idx < N_PROJ_QK) {                       // [Q|K] projection
                const int by = idx >> 4, bx = idx & 15;
                A = xh; B = wqk; C = QK;
                K = DIN; ldA = DIN; ldB = DIN; ldC = 2 * DH;
                bm = by * BM; bn = bx * BN;
                alpha = 1.0f; doExp = 0; pOut = nullptr;
                cnt = &g_cntQK[by];
            } else if (idx < N_PROJ_QK + N_VT) {         // V^T projection
                const int t = idx - N_PROJ_QK;
                const int z = t >> 7, r = t & 127, y = r >> 4, x = r & 15;
                A = wv; B = xh + (size_t)z * SEQ * DIN;
                C = Vt + (size_t)z * DH * SEQ;
                K = DIN; ldA = DIN; ldB = DIN; ldC = SEQ;
                bm = y * BM; bn = x * BN;
                alpha = 1.0f; doExp = 0; pOut = nullptr;
                cnt = &g_cntVt[z * 8 + y];
            } else {                                     // exp-scores
                const int t = idx - (N_PROJ_QK + N_VT);
                const int z = t >> 8, r = t & 255, by = r >> 4, bx = r & 15;
                if (tid == 0) {
                    volatile int* c = g_cntQK;
                    while (c[z * 16 + by] < 16) __nanosleep(64);
                    while (c[z * 16 + bx] < 16) __nanosleep(64);
                }
                __syncthreads();
                A = QK + (size_t)z * SEQ * 2 * DH;
                B = A + DH;
                C = At + (size_t)z * SEQ * SEQ;
                K = DH; ldA = 2 * DH; ldB = 2 * DH; ldC = SEQ;
                bm = by * BM; bn = bx * BN;
                alpha = scale; doExp = 1;
                pOut = part + (size_t)bx * (NB * SEQ) + z * SEQ + bm;
                cnt = &g_cntSc[z * 16 + by];
            }

            gemm_body<true>(A, B, C, K, ldA, ldB, ldC, alpha,
                            bm, bn, doExp, nullptr, pOut);
            __threadfence();
            __syncthreads();
            if (tid == 0) atomicAdd(cnt, 1);
        } else {
            // ----- PV phase (fp32 out, deferred normalization) -----
            const int t = idx - (N_PROJ_QK + N_VT + N_SCORES);
            const int z = t >> 7, r = t & 127, by = r >> 3, bx = r & 7;
            if (tid == 0) {
                volatile int* cs = g_cntSc;
                volatile int* cv = g_cntVt;
                while (cs[z * 16 + by] < 16) __nanosleep(64);
                while (cv[z * 8 + bx] < 16) __nanosleep(64);
            }
            __syncthreads();
            gemm_body<false>(At + (size_t)z * SEQ * SEQ,
                             Vt + (size_t)z * DH * SEQ,
                             out + (size_t)z * SEQ * DH,
                             SEQ, SEQ, SEQ, DH, 1.0f,
                             by * BM, bx * BN, 0,
                             part + (size_t)z * SEQ + by * BM, nullptr);
        }
    }
}

// ---------------------------------------------------------------------------
// Fused fp32 -> fp16 convert for x, Wq, Wk, Wv in ONE launch.
// Block 0 also resets the work queue + dependency counters.
// ---------------------------------------------------------------------------
__global__ __launch_bounds__(256)
void cvt_all_kernel(const float4* __restrict__ x,  uint4* __restrict__ xh,
                    const float4* __restrict__ wq, const float4* __restrict__ wk,
                    uint4* __restrict__ wqk,
                    const float4* __restrict__ wv, uint4* __restrict__ wvh)
{
    const int b = blockIdx.x;
    if (b == 0) {
        if (threadIdx.x == 0) g_qhead = 0;
        for (int i = threadIdx.x; i < 64; i += 256) g_cntQK[i] = 0;
        for (int i = threadIdx.x; i < 32; i += 256) g_cntVt[i] = 0;
        for (int i = threadIdx.x; i < 64; i += 256) g_cntSc[i] = 0;
    }

    const float4* src;
    uint4* dst;
    int off;
    if (b < 4096)      { src = x;  dst = xh;  off = b; }
    else if (b < 4608) { src = wq; dst = wqk; off = b - 4096; }
    else if (b < 5120) { src = wk; dst = wqk + (size_t)(DH * DIN) / 8; off = b - 4608; }
    else               { src = wv; dst = wvh; off = b - 5120; }

    const int i = off * 256 + threadIdx.x;
    const float4 u = src[2 * i], v = src[2 * i + 1];
    __half2 h0 = __float22half2_rn(make_float2(u.x, u.y));
    __half2 h1 = __float22half2_rn(make_float2(u.z, u.w));
    __half2 h2 = __float22half2_rn(make_float2(v.x, v.y));
    __half2 h3 = __float22half2_rn(make_float2(v.z, v.w));
    uint4 o;
    o.x = *reinterpret_cast<uint32_t*>(&h0);
    o.y = *reinterpret_cast<uint32_t*>(&h1);
    o.z = *reinterpret_cast<uint32_t*>(&h2);
    o.w = *reinterpret_cast<uint32_t*>(&h3);
    dst[i] = o;
}

// ---------------------------------------------------------------------------
extern "C" void kernel_launch(void* const* d_in, const int* in_sizes, int n_in,
                              void* d_out, int out_size)
{
    (void)in_sizes; (void)n_in; (void)out_size;

    const float* x  = (const float*)d_in[0];
    const float* Wq = (const float*)d_in[1];
    const float* Wk = (const float*)d_in[2];
    const float* Wv = (const float*)d_in[3];
    float*       out = (float*)d_out;

    __half *xh, *wqk, *wv, *QK, *Vt, *At;
    float *part;
    cudaGetSymbolAddress((void**)&xh,   g_xh);
    cudaGetSymbolAddress((void**)&wqk,  g_Wqk);
    cudaGetSymbolAddress((void**)&wv,   g_Wv);
    cudaGetSymbolAddress((void**)&QK,   g_QK);
    cudaGetSymbolAddress((void**)&Vt,   g_Vt);
    cudaGetSymbolAddress((void**)&At,   g_At);
    cudaGetSymbolAddress((void**)&part, g_Part);

    cudaFuncSetAttribute(attn_queue,
                         cudaFuncAttributeMaxDynamicSharedMemorySize, SMEM_BYTES);

    // 0) convert inputs to fp16 + reset queue/counters (block 0)
    cvt_all_kernel<<<5632, 256>>>((const float4*)x,  (uint4*)xh,
                                  (const float4*)Wq, (const float4*)Wk,
                                  (uint4*)wqk,
                                  (const float4*)Wv, (uint4*)wv);

    // 1) everything else: persistent work-queue kernel
    const float scale = 1.0f / sqrtf((float)SEQ);
    attn_queue<<<304, 256, SMEM_BYTES>>>(xh, wqk, wv, QK, Vt, At,
                                         part, out, scale);
}

// round 17
// speedup vs baseline: 1.1234x; 1.1234x over previous
#include <cuda_runtime.h>
#include <cuda_fp16.h>
#include <cstdint>
#include <math.h>

// Problem shape (fixed)
#define NB   4
#define SEQ  2048
#define DIN  1024
#define DH   1024

// ---------------------------------------------------------------------------
// Scratch (__device__ globals; no allocs allowed)
// ---------------------------------------------------------------------------
__device__ __half g_xh [(size_t)NB * SEQ * DIN];      // fp16 x            (16 MB)
__device__ __half g_Wqk[(size_t)2 * DH * DIN];        // [Wq; Wk] fp16     (4 MB)
__device__ __half g_Wv [(size_t)DH * DIN];            // fp16              (2 MB)
__device__ __half g_QK [(size_t)NB * SEQ * 2 * DH];   // [Q | K] fp16      (32 MB)
__device__ __half g_Vt [(size_t)NB * DH * SEQ];       // V^T fp16          (16 MB)
__device__ __half g_At [(size_t)NB * SEQ * SEQ];      // exp-scores fp16   (32 MB)
__device__ float  g_Part[(size_t)16 * NB * SEQ];      // row partials      (512 KB)

// Dependency counters (reset by cvt block 0 each launch)
__device__ int g_cntQK[64];     // QK row-blocks (z*16+by), target 16
__device__ int g_cntVt[32];     // Vt row-blocks (z*8+y),  target 16
__device__ int g_cntSc[64];     // At row-blocks (z*16+by), target 16

// ---------------------------------------------------------------------------
__device__ __forceinline__ uint32_t smem_u32(const void* p) {
    uint32_t a;
    asm("{ .reg .u64 t; cvta.to.shared.u64 t, %1; cvt.u32.u64 %0, t; }"
        : "=r"(a) : "l"(p));
    return a;
}

#define LDMATRIX_X4(r0, r1, r2, r3, addr)                                      \
    asm volatile("ldmatrix.sync.aligned.m8n8.x4.shared.b16 {%0,%1,%2,%3}, [%4];" \
                 : "=r"(r0), "=r"(r1), "=r"(r2), "=r"(r3) : "r"(addr))

#define PDL_TRIGGER() asm volatile("griddepcontrol.launch_dependents;")

// ---------------------------------------------------------------------------
// fp16 m16n8k16 NT GEMM body (identical to R15).
// ---------------------------------------------------------------------------
constexpr int BM = 128, BN = 128, BK = 64, NST = 3;
constexpr int TILE_H  = BM * BK;
constexpr int STAGE_H = 2 * TILE_H;
constexpr int SMEM_BYTES = NST * STAGE_H * 2;    // 98304 B

template <bool OUT_HALF>
__device__ __forceinline__
void gemm_body(const __half* __restrict__ Ab, const __half* __restrict__ Bb,
               void* __restrict__ Cb, int K,
               int ldA, int ldB, int ldC, float alpha,
               int bm, int bn, int doExp,
               const float* __restrict__ partIn,
               float* __restrict__ partOut)
{
    extern __shared__ __align__(16) __half sm[];

    const int tid  = threadIdx.x;
    const int wid  = tid >> 5;
    const int lane = tid & 31;
    const int g    = lane >> 2;
    const int tig  = lane & 3;

    const int wm = wid >> 2;
    const int wn = wid & 3;
    const int KT = K / BK;

    const uint32_t smem_base = smem_u32(sm);

    const int xorv = lane & 7;
    const int rowA = wm * 64 + (lane & 7) + ((lane >> 3) & 1) * 8;
    const int selA = lane >> 4;
    const int rowB = wn * 32 + (lane & 7) + ((lane >> 4) & 1) * 8;
    const int selB = (lane >> 3) & 1;

#define LOAD_CHUNK(s, i) do {                                                  \
        const uint32_t _base = smem_base + (uint32_t)(((s) % NST) * STAGE_H * 2); \
        const uint32_t _bB   = _base + (uint32_t)(TILE_H * 2);                 \
        const int _idx = (i) * 256 + tid;                                      \
        const int _row = _idx >> 3;                                            \
        const int _seg = _idx & 7;                                             \
        const uint32_t _soff = (uint32_t)(_row * 128 +                         \
                               ((_seg ^ (_row & 7)) << 4));                    \
        const __half* _ga = Ab + (uint32_t)(bm + _row) * (uint32_t)ldA         \
                               + (uint32_t)((s) * BK + _seg * 8);              \
        const __half* _gb = Bb + (uint32_t)(bn + _row) * (uint32_t)ldB         \
                               + (uint32_t)((s) * BK + _seg * 8);              \
        asm volatile("cp.async.cg.shared.global [%0], [%1], 16;"               \
                     :: "r"(_base + _soff), "l"(_ga));                         \
        asm volatile("cp.async.cg.shared.global [%0], [%1], 16;"               \
                     :: "r"(_bB + _soff), "l"(_gb));                           \
    } while (0)

#define LOAD_STAGE(s) do {                                                     \
        LOAD_CHUNK(s, 0); LOAD_CHUNK(s, 1); LOAD_CHUNK(s, 2); LOAD_CHUNK(s, 3);\
        asm volatile("cp.async.commit_group;" ::: "memory");                   \
    } while (0)

    float acc[4][4][4];
    #pragma unroll
    for (int i = 0; i < 4; i++)
        #pragma unroll
        for (int j = 0; j < 4; j++)
            #pragma unroll
            for (int r = 0; r < 4; r++) acc[i][j][r] = 0.0f;

    LOAD_STAGE(0);
    LOAD_STAGE(1);

    for (int k0 = 0; k0 < KT; k0++) {
        if (k0 + 1 < KT) asm volatile("cp.async.wait_group 1;" ::: "memory");
        else             asm volatile("cp.async.wait_group 0;" ::: "memory");
        __syncthreads();

        const bool doLoad = (k0 + 2 < KT);
        const uint32_t stA = smem_base + (uint32_t)((k0 % NST) * STAGE_H * 2);
        const uint32_t stB = stA + (uint32_t)(TILE_H * 2);
        const uint32_t aRowAddr = stA + (uint32_t)(rowA * 128);
        const uint32_t bRowAddr = stB + (uint32_t)(rowB * 128);

        #pragma unroll
        for (int ks = 0; ks < BK / 16; ks++) {
            if (doLoad) {
                LOAD_CHUNK(k0 + 2, ks);
                if (ks == 3)
                    asm volatile("cp.async.commit_group;" ::: "memory");
            }

            const uint32_t offA = (uint32_t)(((2 * ks + selA) ^ xorv) << 4);
            const uint32_t offB = (uint32_t)(((2 * ks + selB) ^ xorv) << 4);
            uint32_t a[4][4], b[4][2];
            #pragma unroll
            for (int p = 0; p < 2; p++)
                LDMATRIX_X4(b[2 * p][0], b[2 * p][1], b[2 * p + 1][0], b[2 * p + 1][1],
                            bRowAddr + (uint32_t)(p * 16 * 128) + offB);
            #pragma unroll
            for (int mf = 0; mf < 4; mf++)
                LDMATRIX_X4(a[mf][0], a[mf][1], a[mf][2], a[mf][3],
                            aRowAddr + (uint32_t)(mf * 16 * 128) + offA);
            #pragma unroll
            for (int mf = 0; mf < 4; mf++)
                #pragma unroll
                for (int nf = 0; nf < 4; nf++)
                    asm volatile(
                        "mma.sync.aligned.m16n8k16.row.col.f32.f16.f16.f32 "
                        "{%0,%1,%2,%3}, {%4,%5,%6,%7}, {%8,%9}, {%0,%1,%2,%3};"
                        : "+f"(acc[mf][nf][0]), "+f"(acc[mf][nf][1]),
                          "+f"(acc[mf][nf][2]), "+f"(acc[mf][nf][3])
                        : "r"(a[mf][0]), "r"(a[mf][1]), "r"(a[mf][2]), "r"(a[mf][3]),
                          "r"(b[nf][0]), "r"(b[nf][1]));
        }
    }
#undef LOAD_STAGE
#undef LOAD_CHUNK

    // Deferred-normalization reciprocal table (fp32-out path only)
    float* sinv = reinterpret_cast<float*>(sm);
    if (!OUT_HALF && partIn) {
        __syncthreads();
        if (tid < 128) {
            float s = 0.0f;
            #pragma unroll
            for (int t = 0; t < 16; t++)
                s += partIn[t * (NB * SEQ) + tid];
            sinv[tid] = 1.0f / s;
        }
        __syncthreads();
    }

    const uint32_t mBase = (uint32_t)(bm + wm * 64 + g);
    const uint32_t nBase = (uint32_t)(bn + wn * 32 + 2 * tig);
    float psum[4][2];
    #pragma unroll
    for (int mf = 0; mf < 4; mf++) { psum[mf][0] = 0.0f; psum[mf][1] = 0.0f; }

    #pragma unroll
    for (int mf = 0; mf < 4; mf++) {
        float ri0 = 1.0f, ri1 = 1.0f;
        if (!OUT_HALF && partIn) {
            ri0 = sinv[wm * 64 + mf * 16 + g];
            ri1 = sinv[wm * 64 + mf * 16 + g + 8];
        }
        #pragma unroll
        for (int nf = 0; nf < 4; nf++) {
            float v0 = acc[mf][nf][0] * alpha, v1 = acc[mf][nf][1] * alpha;
            float v2 = acc[mf][nf][2] * alpha, v3 = acc[mf][nf][3] * alpha;
            if (doExp) {
                v0 = __expf(v0); v1 = __expf(v1);
                v2 = __expf(v2); v3 = __expf(v3);
                psum[mf][0] += v0 + v1;
                psum[mf][1] += v2 + v3;
            }
            const uint32_t r0 = (mBase + mf * 16) * (uint32_t)ldC + nBase + nf * 8;
            const uint32_t r1 = r0 + 8 * (uint32_t)ldC;
            if (OUT_HALF) {
                __half* Ch = (__half*)Cb;
                *reinterpret_cast<__half2*>(&Ch[r0]) =
                    __float22half2_rn(make_float2(v0, v1));
                *reinterpret_cast<__half2*>(&Ch[r1]) =
                    __float22half2_rn(make_float2(v2, v3));
            } else {
                float* Cf = (float*)Cb;
                *reinterpret_cast<float2*>(&Cf[r0]) = make_float2(v0 * ri0, v1 * ri0);
                *reinterpret_cast<float2*>(&Cf[r1]) = make_float2(v2 * ri1, v3 * ri1);
            }
        }
    }

    if (doExp && partOut) {
        #pragma unroll
        for (int mf = 0; mf < 4; mf++) {
            #pragma unroll
            for (int h = 0; h < 2; h++) {
                psum[mf][h] += __shfl_xor_sync(0xFFFFFFFFu, psum[mf][h], 1);
                psum[mf][h] += __shfl_xor_sync(0xFFFFFFFFu, psum[mf][h], 2);
            }
        }
        __syncthreads();
        float* sp = reinterpret_cast<float*>(sm);
        if (tig == 0) {
            #pragma unroll
            for (int mf = 0; mf < 4; mf++) {
                sp[(wm * 64 + mf * 16 + g)     * 4 + wn] = psum[mf][0];
                sp[(wm * 64 + mf * 16 + g + 8) * 4 + wn] = psum[mf][1];
            }
        }
        __syncthreads();
        if (tid < 128) {
            const float* r = sp + tid * 4;
            partOut[tid] = (r[0] + r[1]) + (r[2] + r[3]);
        }
    }
}

// ---------------------------------------------------------------------------
// Phase 1: [Q|K] projection. grid (16, 64). Publishes cntQK[by].
// ---------------------------------------------------------------------------
__global__ __launch_bounds__(256, 2)
void proj_kernel(const __half* __restrict__ xh, const __half* __restrict__ wqk,
                 __half* __restrict__ QK)
{
    PDL_TRIGGER();     // all CTAs resident => dependents may launch
    gemm_body<true>(xh, wqk, QK, DIN, DIN, DIN, 2 * DH, 1.0f,
                    blockIdx.y * BM, blockIdx.x * BN, 0, nullptr, nullptr);
    __threadfence();
    __syncthreads();
    if (threadIdx.x == 0) atomicAdd(&g_cntQK[blockIdx.y], 1);
}

// ---------------------------------------------------------------------------
// Phase 2: Vt + exp-scores. grid (16, 24, NB). PDL-dependent on proj.
//   y<8: Vt tile (no deps). y>=8: scores tile (spins on cntQK).
//   Publishes cntVt / cntSc.
// ---------------------------------------------------------------------------
__global__ __launch_bounds__(256, 2)
void vt_scores_kernel(const __half* __restrict__ xh,
                      const __half* __restrict__ wv,
                      const __half* __restrict__ QK,
                      __half* __restrict__ Vt, __half* __restrict__ At,
                      float* __restrict__ part, float scale)
{
    PDL_TRIGGER();
    const uint32_t z = blockIdx.z;
    const __half* A;  const __half* B;  __half* C;
    int K, ldA, ldB, ldC, bm, doExp;
    float alpha;
    float* pb;
    int* cnt;

    if (blockIdx.y < 8) {              // V^T_b = Wv @ x_b^T
        A = wv;
        B = xh + (size_t)z * (SEQ * DIN);
        C = Vt + (size_t)z * (DH * SEQ);
        K = DIN; ldA = DIN; ldB = DIN; ldC = SEQ;
        bm = blockIdx.y * BM;
        alpha = 1.0f; doExp = 0; pb = nullptr;
        cnt = &g_cntVt[z * 8 + blockIdx.y];
    } else {                            // exp-scores
        const int by = blockIdx.y - 8;
        if (threadIdx.x == 0) {
            volatile int* c = g_cntQK;
            while (c[z * 16 + by] < 16) __nanosleep(64);
            while (c[z * 16 + blockIdx.x] < 16) __nanosleep(64);
        }
        __syncthreads();
        A = QK + (size_t)z * (SEQ * 2 * DH);
        B = A + DH;
        C = At + (size_t)z * (SEQ * SEQ);
        K = DH; ldA = 2 * DH; ldB = 2 * DH; ldC = SEQ;
        bm = by * BM;
        alpha = scale; doExp = 1;
        pb = part + (size_t)blockIdx.x * (NB * SEQ) + z * SEQ + bm;
        cnt = &g_cntSc[z * 16 + by];
    }
    gemm_body<true>(A, B, C, K, ldA, ldB, ldC, alpha, bm, blockIdx.x * BN,
                    doExp, nullptr, pb);
    __threadfence();
    __syncthreads();
    if (threadIdx.x == 0) atomicAdd(cnt, 1);
}

// ---------------------------------------------------------------------------
// Phase 3: PV with deferred normalization. grid (8, 16, NB).
//   PDL-dependent on vt_scores; spins on cntSc/cntVt.
// ---------------------------------------------------------------------------
__global__ __launch_bounds__(256, 2)
void pv_kernel(const __half* __restrict__ At, const __half* __restrict__ Vt,
               float* __restrict__ out, const float* __restrict__ part)
{
    const int z = blockIdx.z, by = blockIdx.y, bx = blockIdx.x;
    if (threadIdx.x == 0) {
        volatile int* cs = g_cntSc;
        volatile int* cv = g_cntVt;
        while (cs[z * 16 + by] < 16) __nanosleep(64);
        while (cv[z * 8 + bx] < 16) __nanosleep(64);
    }
    __syncthreads();
    gemm_body<false>(At + (size_t)z * SEQ * SEQ,
                     Vt + (size_t)z * DH * SEQ,
                     out + (size_t)z * SEQ * DH,
                     SEQ, SEQ, SEQ, DH, 1.0f,
                     by * BM, bx * BN, 0,
                     part + (size_t)z * SEQ + by * BM, nullptr);
}

// ---------------------------------------------------------------------------
// Fused fp32 -> fp16 convert; block 0 also resets dependency counters.
// ---------------------------------------------------------------------------
__global__ __launch_bounds__(256)
void cvt_all_kernel(const float4* __restrict__ x,  uint4* __restrict__ xh,
                    const float4* __restrict__ wq, const float4* __restrict__ wk,
                    uint4* __restrict__ wqk,
                    const float4* __restrict__ wv, uint4* __restrict__ wvh)
{
    const int b = blockIdx.x;
    if (b == 0) {
        for (int i = threadIdx.x; i < 64; i += 256) g_cntQK[i] = 0;
        for (int i = threadIdx.x; i < 32; i += 256) g_cntVt[i] = 0;
        for (int i = threadIdx.x; i < 64; i += 256) g_cntSc[i] = 0;
    }

    const float4* src;
    uint4* dst;
    int off;
    if (b < 4096)      { src = x;  dst = xh;  off = b; }
    else if (b < 4608) { src = wq; dst = wqk; off = b - 4096; }
    else if (b < 5120) { src = wk; dst = wqk + (size_t)(DH * DIN) / 8; off = b - 4608; }
    else               { src = wv; dst = wvh; off = b - 5120; }

    const int i = off * 256 + threadIdx.x;
    const float4 u = src[2 * i], v = src[2 * i + 1];
    __half2 h0 = __float22half2_rn(make_float2(u.x, u.y));
    __half2 h1 = __float22half2_rn(make_float2(u.z, u.w));
    __half2 h2 = __float22half2_rn(make_float2(v.x, v.y));
    __half2 h3 = __float22half2_rn(make_float2(v.z, v.w));
    uint4 o;
    o.x = *reinterpret_cast<uint32_t*>(&h0);
    o.y = *reinterpret_cast<uint32_t*>(&h1);
    o.z = *reinterpret_cast<uint32_t*>(&h2);
    o.w = *reinterpret_cast<uint32_t*>(&h3);
    dst[i] = o;
}

// ---------------------------------------------------------------------------
extern "C" void kernel_launch(void* const* d_in, const int* in_sizes, int n_in,
                              void* d_out, int out_size)
{
    (void)in_sizes; (void)n_in; (void)out_size;

    const float* x  = (const float*)d_in[0];
    const float* Wq = (const float*)d_in[1];
    const float* Wk = (const float*)d_in[2];
    const float* Wv = (const float*)d_in[3];
    float*       out = (float*)d_out;

    __half *xh, *wqk, *wv, *QK, *Vt, *At;
    float *part;
    cudaGetSymbolAddress((void**)&xh,   g_xh);
    cudaGetSymbolAddress((void**)&wqk,  g_Wqk);
    cudaGetSymbolAddress((void**)&wv,   g_Wv);
    cudaGetSymbolAddress((void**)&QK,   g_QK);
    cudaGetSymbolAddress((void**)&Vt,   g_Vt);
    cudaGetSymbolAddress((void**)&At,   g_At);
    cudaGetSymbolAddress((void**)&part, g_Part);

    cudaFuncSetAttribute(proj_kernel,
                         cudaFuncAttributeMaxDynamicSharedMemorySize, SMEM_BYTES);
    cudaFuncSetAttribute(vt_scores_kernel,
                         cudaFuncAttributeMaxDynamicSharedMemorySize, SMEM_BYTES);
    cudaFuncSetAttribute(pv_kernel,
                         cudaFuncAttributeMaxDynamicSharedMemorySize, SMEM_BYTES);

    const float scale = 1.0f / sqrtf((float)SEQ);

    // 0) convert inputs to fp16 + reset counters
    cvt_all_kernel<<<5632, 256>>>((const float4*)x,  (uint4*)xh,
                                  (const float4*)Wq, (const float4*)Wk,
                                  (uint4*)wqk,
                                  (const float4*)Wv, (uint4*)wv);

    // 1) [Q|K] projection
    proj_kernel<<<dim3(16, 64, 1), 256, SMEM_BYTES>>>(xh, wqk, QK);

    // 2) Vt + exp-scores, PDL-dependent on proj
    {
        cudaLaunchConfig_t cfg = {};
        cfg.gridDim  = dim3(16, 24, NB);
        cfg.blockDim = dim3(256, 1, 1);
        cfg.dynamicSmemBytes = SMEM_BYTES;
        cfg.stream = 0;
        cudaLaunchAttribute attr[1];
        attr[0].id = cudaLaunchAttributeProgrammaticStreamSerialization;
        attr[0].val.programmaticStreamSerializationAllowed = 1;
        cfg.attrs = attr;
        cfg.numAttrs = 1;
        cudaLaunchKernelEx(&cfg, vt_scores_kernel,
                           (const __half*)xh, (const __half*)wv,
                           (const __half*)QK, (__half*)Vt, (__half*)At,
                           (float*)part, scale);
    }

    // 3) PV, PDL-dependent on vt_scores
    {
        cudaLaunchConfig_t cfg = {};
        cfg.gridDim  = dim3(8, 16, NB);
        cfg.blockDim = dim3(256, 1, 1);
        cfg.dynamicSmemBytes = SMEM_BYTES;
        cfg.stream = 0;
        cudaLaunchAttribute attr[1];
        attr[0].id = cudaLaunchAttributeProgrammaticStreamSerialization;
        attr[0].val.programmaticStreamSerializationAllowed = 1;
        cfg.attrs = attr;
        cfg.numAttrs = 1;
        cudaLaunchKernelEx(&cfg, pv_kernel,
                           (const __half*)At, (const __half*)Vt,
                           (float*)out, (const float*)part);
    }
}